// round 9
// baseline (speedup 1.0000x reference)
#include <cuda_runtime.h>
#include <cuda_bf16.h>
#include <cuda_fp16.h>
#include <cstdint>
#include <math.h>

#define B_TOTAL 16384
#define NTREE 64
#define NNODES 63
#define NCLS 10

__device__ unsigned char g_xf[128 * 8 * 32768]; // [tile128][kc8][hi16K|lo16K] A-frag order
__device__ unsigned char g_wf[64 * 8 * 16384];  // [tree][kc8][hi8K|lo8K]     B-frag order
__device__ int g_missing[B_TOTAL];
__device__ float g_attn[NTREE * B_TOTAL];

__device__ __forceinline__ uint32_t smem_u32(const void* p) {
    uint32_t a;
    asm("{ .reg .u64 t; cvta.to.shared.u64 t, %1; cvt.u32.u64 %0, t; }" : "=r"(a) : "l"(p));
    return a;
}
#define CP16(s, g) asm volatile("cp.async.cg.shared.global [%0], [%1], 16;" :: "r"(s), "l"(g))
#define CPCOMMIT() asm volatile("cp.async.commit_group;")
#define CPWAIT1() asm volatile("cp.async.wait_group 1;")
#define CPWAIT0() asm volatile("cp.async.wait_group 0;")
#define MMA(c, a, b) asm volatile( \
    "mma.sync.aligned.m16n8k16.row.col.f32.bf16.bf16.f32 " \
    "{%0,%1,%2,%3},{%4,%5,%6,%7},{%8,%9},{%0,%1,%2,%3};" \
    : "+f"((c)[0]), "+f"((c)[1]), "+f"((c)[2]), "+f"((c)[3]) \
    : "r"((a).x), "r"((a).y), "r"((a).z), "r"((a).w), "r"((b).x), "r"((b).y))

// fast sigmoid pair: d = 0.5 + 0.5*tanh(z/2), tanh in f16x2 (1 MUFU / 2 values)
__device__ __forceinline__ void sigmoid2(float z0, float z1, float& d0, float& d1) {
    __half2 hz = __floats2half2_rn(0.5f * z0, 0.5f * z1);
    uint32_t r;
    asm("tanh.approx.f16x2 %0, %1;" : "=r"(r) : "r"(*(uint32_t*)&hz));
    __half2 th = *(__half2*)&r;
    d0 = fmaf(0.5f, __low2float(th), 0.5f);
    d1 = fmaf(0.5f, __high2float(th), 0.5f);
}

// smem layout
#define OFF_X 0u          // 2 x 32768
#define OFF_W 65536u      // 2 x (2 trees x 16384)
#define OFF_LG 131072u    // logits 128x72 floats / pred staging
#define OFF_LEAF 167936u  // 2 x 5120
#define SMEM_SZ 178176u

// ---------- prep x: NaN-clean + bf16 hi/lo in A-fragment order ----------
__global__ __launch_bounds__(256) void k_prep_x(const float* __restrict__ x) {
    __shared__ __align__(16) unsigned char stage[32768];
    const int tile = blockIdx.x >> 3, kc = blockIdx.x & 7, tid = threadIdx.x;
    for (int e = tid; e < 8192; e += 256) {
        int r = e >> 6, j = e & 63;
        int row = tile * 128 + r;
        float v = x[row * 512 + kc * 64 + j];
        if (v != v) { v = 0.f; atomicOr(&g_missing[row], 1); }
        __nv_bfloat16 h = __float2bfloat16(v);
        __nv_bfloat16 l = __float2bfloat16(v - __bfloat162float(h));
        int mtile = r >> 4, row16 = r & 15, g = row16 & 7, half = row16 >> 3;
        int kstep = j >> 4, kk = j & 15, tg = (kk >> 1) & 3, khalf = kk >> 3, klo = kk & 1;
        int t = g * 4 + tg, reg = half + 2 * khalf;
        uint32_t off = (uint32_t)(((kstep * 8 + mtile) * 32 + t) * 16 + reg * 4 + klo * 2);
        *(__nv_bfloat16*)(stage + off) = h;
        *(__nv_bfloat16*)(stage + 16384 + off) = l;
    }
    __syncthreads();
    uint4* dst = (uint4*)(g_xf + (size_t)blockIdx.x * 32768);
    const uint4* src = (const uint4*)stage;
    for (int e = tid; e < 2048; e += 256) dst[e] = src[e];
}

// ---------- prep w: bf16 hi/lo in B-fragment order ----------
__global__ __launch_bounds__(256) void k_prep_w(const float* __restrict__ tw) {
    __shared__ __align__(16) unsigned char stage[16384];
    const int tree = blockIdx.x >> 3, kc = blockIdx.x & 7, tid = threadIdx.x;
    for (int e = tid; e < 4096; e += 256) {
        int n = e >> 6, j = e & 63;
        float v = (n < NNODES) ? tw[((size_t)(tree * NNODES + n)) * 512 + kc * 64 + j] : 0.f;
        __nv_bfloat16 h = __float2bfloat16(v);
        __nv_bfloat16 l = __float2bfloat16(v - __bfloat162float(h));
        int ntile = n >> 3, g = n & 7;
        int kstep = j >> 4, kk = j & 15, tg = (kk >> 1) & 3, regidx = kk >> 3, klo = kk & 1;
        int t = g * 4 + tg;
        uint32_t off = (uint32_t)(((kstep * 8 + ntile) * 32 + t) * 8 + regidx * 4 + klo * 2);
        *(__nv_bfloat16*)(stage + off) = h;
        *(__nv_bfloat16*)(stage + 8192 + off) = l;
    }
    __syncthreads();
    uint4* dst = (uint4*)(g_wf + (size_t)blockIdx.x * 16384);
    const uint4* src = (const uint4*)stage;
    for (int e = tid; e < 1024; e += 256) dst[e] = src[e];
}

// ---------- attention (SIMT) ----------
__global__ __launch_bounds__(256) void k_attn(
    const float* __restrict__ x, const float* __restrict__ w1, const float* __restrict__ b1,
    const float* __restrict__ gamma_, const float* __restrict__ beta_,
    const float* __restrict__ mean_, const float* __restrict__ var_,
    const float* __restrict__ w2, const float* __restrict__ b2, const float* __restrict__ resw)
{
    __shared__ __align__(16) char smem[33792];
    float4* xs4 = (float4*)smem; float* xsf = (float*)smem;
    float4* w1s4 = (float4*)(smem + 9216);
    float4* hs4 = (float4*)smem; float* hsf = (float*)smem; float* ls = (float*)smem;
    const int tx = threadIdx.x, row0 = blockIdx.x * 64;
    const int ct = tx & 15, rt = tx >> 4, c0 = ct * 8, r0 = rt * 4;
    float acc[4][8];
#pragma unroll
    for (int i = 0; i < 4; ++i)
#pragma unroll
        for (int j = 0; j < 8; ++j) acc[i][j] = 0.f;
    const float4* x4 = (const float4*)x;
    const float4* w14 = (const float4*)w1;
    for (int kc = 0; kc < 16; ++kc) {
#pragma unroll
        for (int j = 0; j < 2; ++j) {
            int idx = tx + 256 * j, r = idx >> 3, q = idx & 7;
            xs4[r * 9 + q] = x4[(row0 + r) * 128 + kc * 8 + q];
        }
#pragma unroll
        for (int j = 0; j < 4; ++j) {
            int idx = tx + 256 * j, k = idx >> 5, cq = idx & 31;
            w1s4[k * 33 + cq] = w14[(kc * 32 + k) * 32 + cq];
        }
        __syncthreads();
#pragma unroll 4
        for (int kk = 0; kk < 32; ++kk) {
            float4 b0 = w1s4[kk * 33 + ct * 2], b1q = w1s4[kk * 33 + ct * 2 + 1];
#pragma unroll
            for (int i = 0; i < 4; ++i) {
                float a = xsf[(r0 + i) * 36 + kk];
                acc[i][0] += a * b0.x; acc[i][1] += a * b0.y; acc[i][2] += a * b0.z; acc[i][3] += a * b0.w;
                acc[i][4] += a * b1q.x; acc[i][5] += a * b1q.y; acc[i][6] += a * b1q.z; acc[i][7] += a * b1q.w;
            }
        }
        __syncthreads();
    }
    float sc[8], sh[8], bb[8];
#pragma unroll
    for (int j = 0; j < 8; ++j) {
        int c = c0 + j;
        float s = gamma_[c] * rsqrtf(var_[c] + 1e-5f);
        sc[j] = s; sh[j] = beta_[c] - mean_[c] * s; bb[j] = b1[c];
    }
#pragma unroll
    for (int i = 0; i < 4; ++i) {
        float h[8];
#pragma unroll
        for (int j = 0; j < 8; ++j) { float v = fmaxf(acc[i][j] + bb[j], 0.f); h[j] = v * sc[j] + sh[j]; }
        hs4[(r0 + i) * 33 + ct * 2] = make_float4(h[0], h[1], h[2], h[3]);
        hs4[(r0 + i) * 33 + ct * 2 + 1] = make_float4(h[4], h[5], h[6], h[7]);
    }
    __syncthreads();
    const int tt = tx & 15, rt2 = tx >> 4, t0 = tt * 4, r0b = rt2 * 4;
    float a2[4][4];
#pragma unroll
    for (int i = 0; i < 4; ++i)
#pragma unroll
        for (int j = 0; j < 4; ++j) a2[i][j] = b2[t0 + j];
    const float4* w24 = (const float4*)w2;
#pragma unroll 4
    for (int c = 0; c < 128; ++c) {
        float4 wv = __ldg(&w24[c * 16 + tt]);
#pragma unroll
        for (int i = 0; i < 4; ++i) {
            float h = hsf[(r0b + i) * 132 + c];
            a2[i][0] += h * wv.x; a2[i][1] += h * wv.y; a2[i][2] += h * wv.z; a2[i][3] += h * wv.w;
        }
    }
    __syncthreads();
#pragma unroll
    for (int i = 0; i < 4; ++i)
        *(float4*)&ls[(r0b + i) * 68 + t0] = make_float4(a2[i][0], a2[i][1], a2[i][2], a2[i][3]);
    __syncthreads();
    if (tx < 64) {
        int row = row0 + tx;
        const float* lr = ls + tx * 68;
        float m = -1e30f, s = 0.f;
#pragma unroll 4
        for (int t = 0; t < 64; ++t) m = fmaxf(m, lr[t]);
#pragma unroll 4
        for (int t = 0; t < 64; ++t) s += expf(lr[t] - m);
        float inv = 1.f / s;
#pragma unroll 4
        for (int t = 0; t < 64; ++t) g_attn[t * B_TOTAL + row] = expf(lr[t] - m) * inv * (0.3f * resw[t]);
    }
}

// ---------- k_trees: 512 threads, 16 warps = (2 trees x 4 M x 2 N-halves) ----------
__global__ __launch_bounds__(512, 1) void k_trees(
    const float* __restrict__ tree_b, const float* __restrict__ tree_temp,
    const float* __restrict__ leaf_values, float* __restrict__ out)
{
    extern __shared__ __align__(16) char smp[];
    const uint32_t sm = smem_u32(smp);
    const int tid = threadIdx.x, lane = tid & 31, wid = tid >> 5;
    const int wt = wid & 1;                 // tree within group
    const int wm = (wid >> 1) & 3;          // M tile (32 rows)
    const int wn = (wid >> 3) & 1;          // N half (4 ni each)
    const int row = tid & 127, part = tid >> 7;   // epilogue: 4 threads/row
    const int rowg = blockIdx.x * 128 + row;
    float* lg = (float*)(smp + OFF_LG);           // [128][72]
    const int miss = g_missing[rowg];

    float pred[NCLS];
#pragma unroll
    for (int c = 0; c < NCLS; ++c) pred[c] = 0.f;

    const unsigned char* xbase = g_xf + (size_t)blockIdx.x * 8 * 32768;

    auto issue = [&](int s) {
        const int grp = s >> 3, kc = s & 7;
        const uint32_t buf = (uint32_t)(s & 1);
        const unsigned char* xsrc = xbase + (size_t)kc * 32768;
        const uint32_t xdst = sm + OFF_X + buf * 32768;
#pragma unroll
        for (int j = 0; j < 4; ++j) {
            int ch = tid + 512 * j;
            CP16(xdst + ch * 16, xsrc + ch * 16);
        }
        const unsigned char* wsrc0 = g_wf + (size_t)((grp * 2) * 8 + kc) * 16384;
        const uint32_t wdst = sm + OFF_W + buf * 32768;
#pragma unroll
        for (int j = 0; j < 2; ++j) {
            int ch = tid + 512 * j;
            CP16(wdst + ch * 16, wsrc0 + ch * 16);
            CP16(wdst + 16384 + ch * 16, wsrc0 + 8 * 16384 + ch * 16);
        }
        if (kc == 0) {
            const unsigned char* lsrc = (const unsigned char*)leaf_values + (size_t)grp * 5120;
            uint32_t ldst = sm + OFF_LEAF + (uint32_t)(grp & 1) * 5120;
            if (tid < 320) CP16(ldst + tid * 16, lsrc + tid * 16);
        }
    };

    float acc[2][4][4];
#pragma unroll
    for (int mi = 0; mi < 2; ++mi)
#pragma unroll
        for (int ni = 0; ni < 4; ++ni)
#pragma unroll
            for (int q = 0; q < 4; ++q) acc[mi][ni][q] = 0.f;

    issue(0);
    CPCOMMIT();

    for (int s = 0; s < 256; ++s) {
        if (s + 1 < 256) { issue(s + 1); CPCOMMIT(); CPWAIT1(); }
        else CPWAIT0();
        __syncthreads();
        const char* bx = smp + OFF_X + (s & 1) * 32768;
        const char* bw = smp + OFF_W + (s & 1) * 32768 + wt * 16384;
#pragma unroll
        for (int ks = 0; ks < 4; ++ks) {
            uint4 ah[2], al[2];
#pragma unroll
            for (int mi = 0; mi < 2; ++mi) {
                uint32_t o = (uint32_t)(((ks * 8 + wm * 2 + mi) * 32 + lane) * 16);
                ah[mi] = *(const uint4*)(bx + o);
                al[mi] = *(const uint4*)(bx + 16384 + o);
            }
#pragma unroll
            for (int ni = 0; ni < 4; ++ni) {
                uint32_t o = (uint32_t)(((ks * 8 + wn * 4 + ni) * 32 + lane) * 8);
                uint2 bh = *(const uint2*)(bw + o);
                uint2 bl = *(const uint2*)(bw + 8192 + o);
#pragma unroll
                for (int mi = 0; mi < 2; ++mi) {
                    MMA(acc[mi][ni], ah[mi], bh);
                    MMA(acc[mi][ni], ah[mi], bl);
                    MMA(acc[mi][ni], al[mi], bh);
                }
            }
        }
        __syncthreads();

        if ((s & 7) == 7) {
            const int grp = s >> 3;
            for (int tt = 0; tt < 2; ++tt) {
                const int t = grp * 2 + tt;
                if (wt == tt) {
#pragma unroll
                    for (int mi = 0; mi < 2; ++mi)
#pragma unroll
                        for (int ni = 0; ni < 4; ++ni) {
                            int r0 = wm * 32 + mi * 16 + (lane >> 2);
                            int c0 = wn * 32 + ni * 8 + (lane & 3) * 2;
                            *(float2*)&lg[r0 * 72 + c0] = make_float2(acc[mi][ni][0], acc[mi][ni][1]);
                            *(float2*)&lg[(r0 + 8) * 72 + c0] = make_float2(acc[mi][ni][2], acc[mi][ni][3]);
                        }
                }
                __syncthreads();
                {
                    // sigmoid via tanh.approx.f16x2: 1 MUFU per 2 nodes
                    float invt = 1.f / tree_temp[t];
                    const float* tbp = tree_b + t * NNODES;
#pragma unroll
                    for (int j = 0; j < 16; j += 2) {
                        int n0 = part * 16 + j, n1 = n0 + 1;
                        int b0i = n0 < NNODES ? n0 : NNODES - 1;
                        int b1i = n1 < NNODES ? n1 : NNODES - 1;
                        float z0 = (lg[row * 72 + n0] + tbp[b0i]) * invt;
                        float z1 = (lg[row * 72 + n1] + tbp[b1i]) * invt;
                        float d0, d1;
                        sigmoid2(z0, z1, d0, d1);
                        lg[row * 72 + n0] = miss ? 0.5f : d0;
                        lg[row * 72 + n1] = miss ? 0.5f : d1;
                    }
                }
                __syncthreads();
                {
                    const float* dp = lg + row * 72;
                    const float* lf = (const float*)(smp + OFF_LEAF + (grp & 1) * 5120) + tt * 640;
                    float d0 = dp[0], d1 = dp[1], d2 = dp[2];
                    float r2[2], r4[4], r8[8];
                    r2[0] = d0; r2[1] = 1.f - d0;
                    r4[0] = r2[0] * d1; r4[2] = r2[0] - r4[0];
                    r4[1] = r2[1] * d2; r4[3] = r2[1] - r4[1];
#pragma unroll
                    for (int j = 0; j < 4; ++j) {
                        float d = dp[3 + j];
                        r8[j] = r4[j] * d; r8[j + 4] = r4[j] - r8[j];
                    }
                    float o[NCLS];
#pragma unroll
                    for (int c = 0; c < NCLS; ++c) o[c] = 0.f;
#pragma unroll
                    for (int j = 0; j < 8; ++j) {
                        int i = part * 8 + j;
                        float f3 = dp[7 + (i & 7)];   if ((i >> 3) & 1) f3 = 1.f - f3;
                        float f4 = dp[15 + (i & 15)]; if ((i >> 4) & 1) f4 = 1.f - f4;
                        float rr = r8[i & 7] * f3 * f4;
                        float d5 = dp[31 + i];
                        float pL = rr * d5, pR = rr - pL;
                        const float* lL = lf + i * 10;
                        const float* lR = lf + (i + 32) * 10;
#pragma unroll
                        for (int c = 0; c < NCLS; ++c) o[c] += pL * lL[c] + pR * lR[c];
                    }
                    float at = g_attn[t * B_TOTAL + rowg];
#pragma unroll
                    for (int c = 0; c < NCLS; ++c) pred[c] += at * o[c];
                }
                __syncthreads();
            }
#pragma unroll
            for (int mi = 0; mi < 2; ++mi)
#pragma unroll
                for (int ni = 0; ni < 4; ++ni)
#pragma unroll
                    for (int q = 0; q < 4; ++q) acc[mi][ni][q] = 0.f;
        }
    }

    // combine 4 parts + softmax
    float* pred_s = lg;   // 4 x 128 x 10 = 20K < 36K
#pragma unroll
    for (int c = 0; c < NCLS; ++c) pred_s[part * 1280 + row * 10 + c] = pred[c];
    __syncthreads();
    if (tid < 128) {
#pragma unroll
        for (int c = 0; c < NCLS; ++c)
            pred[c] = pred_s[row * 10 + c] + pred_s[1280 + row * 10 + c]
                    + pred_s[2560 + row * 10 + c] + pred_s[3840 + row * 10 + c];
        float m = pred[0];
#pragma unroll
        for (int c = 1; c < NCLS; ++c) m = fmaxf(m, pred[c]);
        float e[NCLS], s = 0.f;
#pragma unroll
        for (int c = 0; c < NCLS; ++c) { e[c] = expf(pred[c] - m); s += e[c]; }
        float inv = 1.f / s;
#pragma unroll
        for (int c = 0; c < NCLS; ++c) out[rowg * 10 + c] = e[c] * inv;
    }
}

// ---------- launcher ----------
extern "C" void kernel_launch(void* const* d_in, const int* in_sizes, int n_in,
                              void* d_out, int out_size) {
    const float* x = (const float*)d_in[0];
    const float* w1 = (const float*)d_in[1];
    const float* b1 = (const float*)d_in[2];
    const float* gm = (const float*)d_in[3];
    const float* bt = (const float*)d_in[4];
    const float* mn = (const float*)d_in[5];
    const float* vr = (const float*)d_in[6];
    const float* w2 = (const float*)d_in[7];
    const float* b2 = (const float*)d_in[8];
    const float* tw = (const float*)d_in[9];
    const float* tb = (const float*)d_in[10];
    const float* tt = (const float*)d_in[11];
    const float* lv = (const float*)d_in[12];
    const float* rw = (const float*)d_in[13];
    cudaFuncSetAttribute(k_trees, cudaFuncAttributeMaxDynamicSharedMemorySize, SMEM_SZ);
    k_prep_x<<<1024, 256>>>(x);
    k_prep_w<<<512, 256>>>(tw);
    k_attn<<<B_TOTAL / 64, 256>>>(x, w1, b1, gm, bt, mn, vr, w2, b2, rw);
    k_trees<<<128, 512, SMEM_SZ>>>(tb, tt, lv, (float*)d_out);
}

// round 10
// speedup vs baseline: 1.2213x; 1.2213x over previous
#include <cuda_runtime.h>
#include <cuda_bf16.h>
#include <cstdint>
#include <math.h>

#define B_TOTAL 16384
#define NTREE 64
#define NNODES 63
#define NCLS 10

__device__ unsigned char g_xf[128 * 8 * 16384]; // [tile128][kc8][hi 16K] A-frag order
__device__ unsigned char g_wf[64 * 8 * 16384];  // [tree][kc8][interleaved hi|lo 16B] B-frag order
__device__ int g_missing[B_TOTAL];
__device__ float g_attn[NTREE * B_TOTAL];

__device__ __forceinline__ uint32_t smem_u32(const void* p) {
    uint32_t a;
    asm("{ .reg .u64 t; cvta.to.shared.u64 t, %1; cvt.u32.u64 %0, t; }" : "=r"(a) : "l"(p));
    return a;
}
#define CP16(s, g) asm volatile("cp.async.cg.shared.global [%0], [%1], 16;" :: "r"(s), "l"(g))
#define CPCOMMIT() asm volatile("cp.async.commit_group;")
#define CPWAIT1() asm volatile("cp.async.wait_group 1;")
#define CPWAIT0() asm volatile("cp.async.wait_group 0;")
#define MMA2(c, a, b0, b1) asm volatile( \
    "mma.sync.aligned.m16n8k16.row.col.f32.bf16.bf16.f32 " \
    "{%0,%1,%2,%3},{%4,%5,%6,%7},{%8,%9},{%0,%1,%2,%3};" \
    : "+f"((c)[0]), "+f"((c)[1]), "+f"((c)[2]), "+f"((c)[3]) \
    : "r"((a).x), "r"((a).y), "r"((a).z), "r"((a).w), "r"(b0), "r"(b1))

// smem layout
#define OFF_X 0u          // 2 x 16384
#define OFF_W 32768u      // 2 x 32768 (2 trees x 16KB)
#define OFF_LG 98304u     // logits 128x72 floats / pred staging (36864)
#define OFF_LEAF 135168u  // 2 x 5120
#define SMEM_SZ 145408u

// ---------- prep x: NaN-clean + bf16 hi in A-fragment order ----------
__global__ __launch_bounds__(256) void k_prep_x(const float* __restrict__ x) {
    __shared__ __align__(16) unsigned char stage[16384];
    const int tile = blockIdx.x >> 3, kc = blockIdx.x & 7, tid = threadIdx.x;
    for (int e = tid; e < 8192; e += 256) {
        int r = e >> 6, j = e & 63;
        int row = tile * 128 + r;
        float v = x[row * 512 + kc * 64 + j];
        if (v != v) { v = 0.f; atomicOr(&g_missing[row], 1); }
        __nv_bfloat16 h = __float2bfloat16(v);
        int mtile = r >> 4, row16 = r & 15, g = row16 & 7, half = row16 >> 3;
        int kstep = j >> 4, kk = j & 15, tg = (kk >> 1) & 3, khalf = kk >> 3, klo = kk & 1;
        int t = g * 4 + tg, reg = half + 2 * khalf;
        uint32_t off = (uint32_t)(((kstep * 8 + mtile) * 32 + t) * 16 + reg * 4 + klo * 2);
        *(__nv_bfloat16*)(stage + off) = h;
    }
    __syncthreads();
    uint4* dst = (uint4*)(g_xf + (size_t)blockIdx.x * 16384);
    const uint4* src = (const uint4*)stage;
    for (int e = tid; e < 1024; e += 256) dst[e] = src[e];
}

// ---------- prep w: bf16 hi/lo interleaved (16B per ks/ntile/lane) B-frag order ----------
__global__ __launch_bounds__(256) void k_prep_w(const float* __restrict__ tw) {
    __shared__ __align__(16) unsigned char stage[16384];
    const int tree = blockIdx.x >> 3, kc = blockIdx.x & 7, tid = threadIdx.x;
    for (int e = tid; e < 4096; e += 256) {
        int n = e >> 6, j = e & 63;
        float v = (n < NNODES) ? tw[((size_t)(tree * NNODES + n)) * 512 + kc * 64 + j] : 0.f;
        __nv_bfloat16 h = __float2bfloat16(v);
        __nv_bfloat16 l = __float2bfloat16(v - __bfloat162float(h));
        int ntile = n >> 3, g = n & 7;
        int kstep = j >> 4, kk = j & 15, tg = (kk >> 1) & 3, regidx = kk >> 3, klo = kk & 1;
        int t = g * 4 + tg;
        uint32_t off = (uint32_t)(((kstep * 8 + ntile) * 32 + t) * 16 + regidx * 4 + klo * 2);
        *(__nv_bfloat16*)(stage + off) = h;       // hi in bytes 0-7
        *(__nv_bfloat16*)(stage + off + 8) = l;   // lo in bytes 8-15
    }
    __syncthreads();
    uint4* dst = (uint4*)(g_wf + (size_t)blockIdx.x * 16384);
    const uint4* src = (const uint4*)stage;
    for (int e = tid; e < 1024; e += 256) dst[e] = src[e];
}

// ---------- attention (SIMT) ----------
__global__ __launch_bounds__(256) void k_attn(
    const float* __restrict__ x, const float* __restrict__ w1, const float* __restrict__ b1,
    const float* __restrict__ gamma_, const float* __restrict__ beta_,
    const float* __restrict__ mean_, const float* __restrict__ var_,
    const float* __restrict__ w2, const float* __restrict__ b2, const float* __restrict__ resw)
{
    __shared__ __align__(16) char smem[33792];
    float4* xs4 = (float4*)smem; float* xsf = (float*)smem;
    float4* w1s4 = (float4*)(smem + 9216);
    float4* hs4 = (float4*)smem; float* hsf = (float*)smem; float* ls = (float*)smem;
    const int tx = threadIdx.x, row0 = blockIdx.x * 64;
    const int ct = tx & 15, rt = tx >> 4, c0 = ct * 8, r0 = rt * 4;
    float acc[4][8];
#pragma unroll
    for (int i = 0; i < 4; ++i)
#pragma unroll
        for (int j = 0; j < 8; ++j) acc[i][j] = 0.f;
    const float4* x4 = (const float4*)x;
    const float4* w14 = (const float4*)w1;
    for (int kc = 0; kc < 16; ++kc) {
#pragma unroll
        for (int j = 0; j < 2; ++j) {
            int idx = tx + 256 * j, r = idx >> 3, q = idx & 7;
            xs4[r * 9 + q] = x4[(row0 + r) * 128 + kc * 8 + q];
        }
#pragma unroll
        for (int j = 0; j < 4; ++j) {
            int idx = tx + 256 * j, k = idx >> 5, cq = idx & 31;
            w1s4[k * 33 + cq] = w14[(kc * 32 + k) * 32 + cq];
        }
        __syncthreads();
#pragma unroll 4
        for (int kk = 0; kk < 32; ++kk) {
            float4 b0 = w1s4[kk * 33 + ct * 2], b1q = w1s4[kk * 33 + ct * 2 + 1];
#pragma unroll
            for (int i = 0; i < 4; ++i) {
                float a = xsf[(r0 + i) * 36 + kk];
                acc[i][0] += a * b0.x; acc[i][1] += a * b0.y; acc[i][2] += a * b0.z; acc[i][3] += a * b0.w;
                acc[i][4] += a * b1q.x; acc[i][5] += a * b1q.y; acc[i][6] += a * b1q.z; acc[i][7] += a * b1q.w;
            }
        }
        __syncthreads();
    }
    float sc[8], sh[8], bb[8];
#pragma unroll
    for (int j = 0; j < 8; ++j) {
        int c = c0 + j;
        float s = gamma_[c] * rsqrtf(var_[c] + 1e-5f);
        sc[j] = s; sh[j] = beta_[c] - mean_[c] * s; bb[j] = b1[c];
    }
#pragma unroll
    for (int i = 0; i < 4; ++i) {
        float h[8];
#pragma unroll
        for (int j = 0; j < 8; ++j) { float v = fmaxf(acc[i][j] + bb[j], 0.f); h[j] = v * sc[j] + sh[j]; }
        hs4[(r0 + i) * 33 + ct * 2] = make_float4(h[0], h[1], h[2], h[3]);
        hs4[(r0 + i) * 33 + ct * 2 + 1] = make_float4(h[4], h[5], h[6], h[7]);
    }
    __syncthreads();
    const int tt = tx & 15, rt2 = tx >> 4, t0 = tt * 4, r0b = rt2 * 4;
    float a2[4][4];
#pragma unroll
    for (int i = 0; i < 4; ++i)
#pragma unroll
        for (int j = 0; j < 4; ++j) a2[i][j] = b2[t0 + j];
    const float4* w24 = (const float4*)w2;
#pragma unroll 4
    for (int c = 0; c < 128; ++c) {
        float4 wv = __ldg(&w24[c * 16 + tt]);
#pragma unroll
        for (int i = 0; i < 4; ++i) {
            float h = hsf[(r0b + i) * 132 + c];
            a2[i][0] += h * wv.x; a2[i][1] += h * wv.y; a2[i][2] += h * wv.z; a2[i][3] += h * wv.w;
        }
    }
    __syncthreads();
#pragma unroll
    for (int i = 0; i < 4; ++i)
        *(float4*)&ls[(r0b + i) * 68 + t0] = make_float4(a2[i][0], a2[i][1], a2[i][2], a2[i][3]);
    __syncthreads();
    if (tx < 64) {
        int row = row0 + tx;
        const float* lr = ls + tx * 68;
        float m = -1e30f, s = 0.f;
#pragma unroll 4
        for (int t = 0; t < 64; ++t) m = fmaxf(m, lr[t]);
#pragma unroll 4
        for (int t = 0; t < 64; ++t) s += expf(lr[t] - m);
        float inv = 1.f / s;
#pragma unroll 4
        for (int t = 0; t < 64; ++t) g_attn[t * B_TOTAL + row] = expf(lr[t] - m) * inv * (0.3f * resw[t]);
    }
}

// ---------- k_trees: 512 threads, 2-pass (x-hi x w-hi/lo) ----------
__global__ __launch_bounds__(512, 1) void k_trees(
    const float* __restrict__ tree_b, const float* __restrict__ tree_temp,
    const float* __restrict__ leaf_values, float* __restrict__ out)
{
    extern __shared__ __align__(16) char smp[];
    const uint32_t sm = smem_u32(smp);
    const int tid = threadIdx.x, lane = tid & 31, wid = tid >> 5;
    const int wt = wid & 1;                 // tree within group
    const int wm = (wid >> 1) & 3;          // M tile (32 rows)
    const int wn = (wid >> 3) & 1;          // N half (4 ni each)
    const int row = tid & 127, part = tid >> 7;   // epilogue: 4 threads/row
    const int rowg = blockIdx.x * 128 + row;
    float* lg = (float*)(smp + OFF_LG);           // [128][72]
    const int miss = g_missing[rowg];

    float pred[NCLS];
#pragma unroll
    for (int c = 0; c < NCLS; ++c) pred[c] = 0.f;

    const unsigned char* xbase = g_xf + (size_t)blockIdx.x * 8 * 16384;

    auto issue = [&](int s) {
        const int grp = s >> 3, kc = s & 7;
        const uint32_t buf = (uint32_t)(s & 1);
        const unsigned char* xsrc = xbase + (size_t)kc * 16384;
        const uint32_t xdst = sm + OFF_X + buf * 16384;
#pragma unroll
        for (int j = 0; j < 2; ++j) {
            int ch = tid + 512 * j;
            CP16(xdst + ch * 16, xsrc + ch * 16);
        }
        const unsigned char* wsrc0 = g_wf + (size_t)((grp * 2) * 8 + kc) * 16384;
        const uint32_t wdst = sm + OFF_W + buf * 32768;
#pragma unroll
        for (int j = 0; j < 2; ++j) {
            int ch = tid + 512 * j;
            CP16(wdst + ch * 16, wsrc0 + ch * 16);
            CP16(wdst + 16384 + ch * 16, wsrc0 + 8 * 16384 + ch * 16);
        }
        if (kc == 0) {
            const unsigned char* lsrc = (const unsigned char*)leaf_values + (size_t)grp * 5120;
            uint32_t ldst = sm + OFF_LEAF + (uint32_t)(grp & 1) * 5120;
            if (tid < 320) CP16(ldst + tid * 16, lsrc + tid * 16);
        }
    };

    float acc[2][4][4];
#pragma unroll
    for (int mi = 0; mi < 2; ++mi)
#pragma unroll
        for (int ni = 0; ni < 4; ++ni)
#pragma unroll
            for (int q = 0; q < 4; ++q) acc[mi][ni][q] = 0.f;

    issue(0);
    CPCOMMIT();

    for (int s = 0; s < 256; ++s) {
        if (s + 1 < 256) { issue(s + 1); CPCOMMIT(); CPWAIT1(); }
        else CPWAIT0();
        __syncthreads();
        const char* bx = smp + OFF_X + (s & 1) * 16384;
        const char* bw = smp + OFF_W + (s & 1) * 32768 + wt * 16384;
#pragma unroll
        for (int ks = 0; ks < 4; ++ks) {
            uint4 ah[2];
#pragma unroll
            for (int mi = 0; mi < 2; ++mi)
                ah[mi] = *(const uint4*)(bx + (uint32_t)(((ks * 8 + wm * 2 + mi) * 32 + lane) * 16));
#pragma unroll
            for (int ni = 0; ni < 4; ++ni) {
                uint4 b = *(const uint4*)(bw + (uint32_t)(((ks * 8 + wn * 4 + ni) * 32 + lane) * 16));
#pragma unroll
                for (int mi = 0; mi < 2; ++mi) {
                    MMA2(acc[mi][ni], ah[mi], b.x, b.y);   // a_hi * b_hi
                    MMA2(acc[mi][ni], ah[mi], b.z, b.w);   // a_hi * b_lo
                }
            }
        }
        __syncthreads();

        if ((s & 7) == 7) {
            const int grp = s >> 3;
            for (int tt = 0; tt < 2; ++tt) {
                const int t = grp * 2 + tt;
                if (wt == tt) {
#pragma unroll
                    for (int mi = 0; mi < 2; ++mi)
#pragma unroll
                        for (int ni = 0; ni < 4; ++ni) {
                            int r0 = wm * 32 + mi * 16 + (lane >> 2);
                            int c0 = wn * 32 + ni * 8 + (lane & 3) * 2;
                            *(float2*)&lg[r0 * 72 + c0] = make_float2(acc[mi][ni][0], acc[mi][ni][1]);
                            *(float2*)&lg[(r0 + 8) * 72 + c0] = make_float2(acc[mi][ni][2], acc[mi][ni][3]);
                        }
                }
                __syncthreads();
                {
                    float invt = 1.f / tree_temp[t];
#pragma unroll
                    for (int j = 0; j < 16; ++j) {
                        int n = part * 16 + j;
                        if (n < NNODES) {
                            float z = (lg[row * 72 + n] + tree_b[t * NNODES + n]) * invt;
                            z = fminf(fmaxf(z, -30.f), 30.f);
                            float d = __fdividef(1.f, 1.f + __expf(-z));
                            lg[row * 72 + n] = miss ? 0.5f : d;
                        }
                    }
                }
                __syncthreads();
                {
                    const float* dp = lg + row * 72;
                    const float* lf = (const float*)(smp + OFF_LEAF + (grp & 1) * 5120) + tt * 640;
                    float d0 = dp[0], d1 = dp[1], d2 = dp[2];
                    float r2[2], r4[4], r8[8];
                    r2[0] = d0; r2[1] = 1.f - d0;
                    r4[0] = r2[0] * d1; r4[2] = r2[0] - r4[0];
                    r4[1] = r2[1] * d2; r4[3] = r2[1] - r4[1];
#pragma unroll
                    for (int j = 0; j < 4; ++j) {
                        float d = dp[3 + j];
                        r8[j] = r4[j] * d; r8[j + 4] = r4[j] - r8[j];
                    }
                    float o[NCLS];
#pragma unroll
                    for (int c = 0; c < NCLS; ++c) o[c] = 0.f;
#pragma unroll
                    for (int j = 0; j < 8; ++j) {
                        int i = part * 8 + j;
                        float f3 = dp[7 + (i & 7)];   if ((i >> 3) & 1) f3 = 1.f - f3;
                        float f4 = dp[15 + (i & 15)]; if ((i >> 4) & 1) f4 = 1.f - f4;
                        float rr = r8[i & 7] * f3 * f4;
                        float d5 = dp[31 + i];
                        float pL = rr * d5, pR = rr - pL;
                        const float* lL = lf + i * 10;
                        const float* lR = lf + (i + 32) * 10;
#pragma unroll
                        for (int c = 0; c < NCLS; ++c) o[c] += pL * lL[c] + pR * lR[c];
                    }
                    float at = g_attn[t * B_TOTAL + rowg];
#pragma unroll
                    for (int c = 0; c < NCLS; ++c) pred[c] += at * o[c];
                }
                __syncthreads();
            }
#pragma unroll
            for (int mi = 0; mi < 2; ++mi)
#pragma unroll
                for (int ni = 0; ni < 4; ++ni)
#pragma unroll
                    for (int q = 0; q < 4; ++q) acc[mi][ni][q] = 0.f;
        }
    }

    // combine 4 parts + softmax
    float* pred_s = lg;   // 4 x 128 x 10 = 20K < 36K
#pragma unroll
    for (int c = 0; c < NCLS; ++c) pred_s[part * 1280 + row * 10 + c] = pred[c];
    __syncthreads();
    if (tid < 128) {
#pragma unroll
        for (int c = 0; c < NCLS; ++c)
            pred[c] = pred_s[row * 10 + c] + pred_s[1280 + row * 10 + c]
                    + pred_s[2560 + row * 10 + c] + pred_s[3840 + row * 10 + c];
        float m = pred[0];
#pragma unroll
        for (int c = 1; c < NCLS; ++c) m = fmaxf(m, pred[c]);
        float e[NCLS], s = 0.f;
#pragma unroll
        for (int c = 0; c < NCLS; ++c) { e[c] = expf(pred[c] - m); s += e[c]; }
        float inv = 1.f / s;
#pragma unroll
        for (int c = 0; c < NCLS; ++c) out[rowg * 10 + c] = e[c] * inv;
    }
}

// ---------- launcher ----------
extern "C" void kernel_launch(void* const* d_in, const int* in_sizes, int n_in,
                              void* d_out, int out_size) {
    const float* x = (const float*)d_in[0];
    const float* w1 = (const float*)d_in[1];
    const float* b1 = (const float*)d_in[2];
    const float* gm = (const float*)d_in[3];
    const float* bt = (const float*)d_in[4];
    const float* mn = (const float*)d_in[5];
    const float* vr = (const float*)d_in[6];
    const float* w2 = (const float*)d_in[7];
    const float* b2 = (const float*)d_in[8];
    const float* tw = (const float*)d_in[9];
    const float* tb = (const float*)d_in[10];
    const float* tt = (const float*)d_in[11];
    const float* lv = (const float*)d_in[12];
    const float* rw = (const float*)d_in[13];
    cudaFuncSetAttribute(k_trees, cudaFuncAttributeMaxDynamicSharedMemorySize, SMEM_SZ);
    k_prep_x<<<1024, 256>>>(x);
    k_prep_w<<<512, 256>>>(tw);
    k_attn<<<B_TOTAL / 64, 256>>>(x, w1, b1, gm, bt, mn, vr, w2, b2, rw);
    k_trees<<<128, 512, SMEM_SZ>>>(tb, tt, lv, (float*)d_out);
}

// round 11
// speedup vs baseline: 1.6180x; 1.3249x over previous
#include <cuda_runtime.h>
#include <cuda_bf16.h>
#include <cstdint>
#include <math.h>

#define B_TOTAL 16384
#define NTREE 64
#define NNODES 63
#define NCLS 10

__device__ unsigned char g_xf[128 * 8 * 16384]; // [tile128][kc8][hi 16K] A-frag order
__device__ unsigned char g_wf[64 * 8 * 8192];   // [tree][kc8][hi 8K]     B-frag order
__device__ int g_missing[B_TOTAL];
__device__ float g_attn[NTREE * B_TOTAL];

__device__ __forceinline__ uint32_t smem_u32(const void* p) {
    uint32_t a;
    asm("{ .reg .u64 t; cvta.to.shared.u64 t, %1; cvt.u32.u64 %0, t; }" : "=r"(a) : "l"(p));
    return a;
}
#define CP16(s, g) asm volatile("cp.async.cg.shared.global [%0], [%1], 16;" :: "r"(s), "l"(g))
#define CPCOMMIT() asm volatile("cp.async.commit_group;")
#define CPWAIT1() asm volatile("cp.async.wait_group 1;")
#define CPWAIT0() asm volatile("cp.async.wait_group 0;")
#define MMA2(c, a, b0, b1) asm volatile( \
    "mma.sync.aligned.m16n8k16.row.col.f32.bf16.bf16.f32 " \
    "{%0,%1,%2,%3},{%4,%5,%6,%7},{%8,%9},{%0,%1,%2,%3};" \
    : "+f"((c)[0]), "+f"((c)[1]), "+f"((c)[2]), "+f"((c)[3]) \
    : "r"((a).x), "r"((a).y), "r"((a).z), "r"((a).w), "r"(b0), "r"(b1))

// smem layout
#define OFF_X 0u          // 2 x 32768 (2 kc per stage)
#define OFF_W 65536u      // 2 x 32768 (2 trees x 16KB [2 kc])
#define OFF_LG 131072u    // logits 128x72 floats / pred staging (36864)
#define OFF_LEAF 167936u  // 2 x 5120
#define SMEM_SZ 178176u

// ---------- prep x: NaN-clean + bf16 hi in A-fragment order ----------
__global__ __launch_bounds__(256) void k_prep_x(const float* __restrict__ x) {
    __shared__ __align__(16) unsigned char stage[16384];
    const int tile = blockIdx.x >> 3, kc = blockIdx.x & 7, tid = threadIdx.x;
    for (int e = tid; e < 8192; e += 256) {
        int r = e >> 6, j = e & 63;
        int row = tile * 128 + r;
        float v = x[row * 512 + kc * 64 + j];
        if (v != v) { v = 0.f; atomicOr(&g_missing[row], 1); }
        __nv_bfloat16 h = __float2bfloat16(v);
        int mtile = r >> 4, row16 = r & 15, g = row16 & 7, half = row16 >> 3;
        int kstep = j >> 4, kk = j & 15, tg = (kk >> 1) & 3, khalf = kk >> 3, klo = kk & 1;
        int t = g * 4 + tg, reg = half + 2 * khalf;
        uint32_t off = (uint32_t)(((kstep * 8 + mtile) * 32 + t) * 16 + reg * 4 + klo * 2);
        *(__nv_bfloat16*)(stage + off) = h;
    }
    __syncthreads();
    uint4* dst = (uint4*)(g_xf + (size_t)blockIdx.x * 16384);
    const uint4* src = (const uint4*)stage;
    for (int e = tid; e < 1024; e += 256) dst[e] = src[e];
}

// ---------- prep w: bf16 hi in B-fragment order ----------
__global__ __launch_bounds__(256) void k_prep_w(const float* __restrict__ tw) {
    __shared__ __align__(16) unsigned char stage[8192];
    const int tree = blockIdx.x >> 3, kc = blockIdx.x & 7, tid = threadIdx.x;
    for (int e = tid; e < 4096; e += 256) {
        int n = e >> 6, j = e & 63;
        float v = (n < NNODES) ? tw[((size_t)(tree * NNODES + n)) * 512 + kc * 64 + j] : 0.f;
        __nv_bfloat16 h = __float2bfloat16(v);
        int ntile = n >> 3, g = n & 7;
        int kstep = j >> 4, kk = j & 15, tg = (kk >> 1) & 3, regidx = kk >> 3, klo = kk & 1;
        int t = g * 4 + tg;
        uint32_t off = (uint32_t)(((kstep * 8 + ntile) * 32 + t) * 8 + regidx * 4 + klo * 2);
        *(__nv_bfloat16*)(stage + off) = h;
    }
    __syncthreads();
    uint4* dst = (uint4*)(g_wf + (size_t)blockIdx.x * 8192);
    const uint4* src = (const uint4*)stage;
    for (int e = tid; e < 512; e += 256) dst[e] = src[e];
}

// ---------- attention (SIMT) ----------
__global__ __launch_bounds__(256) void k_attn(
    const float* __restrict__ x, const float* __restrict__ w1, const float* __restrict__ b1,
    const float* __restrict__ gamma_, const float* __restrict__ beta_,
    const float* __restrict__ mean_, const float* __restrict__ var_,
    const float* __restrict__ w2, const float* __restrict__ b2, const float* __restrict__ resw)
{
    __shared__ __align__(16) char smem[33792];
    float4* xs4 = (float4*)smem; float* xsf = (float*)smem;
    float4* w1s4 = (float4*)(smem + 9216);
    float4* hs4 = (float4*)smem; float* hsf = (float*)smem; float* ls = (float*)smem;
    const int tx = threadIdx.x, row0 = blockIdx.x * 64;
    const int ct = tx & 15, rt = tx >> 4, c0 = ct * 8, r0 = rt * 4;
    float acc[4][8];
#pragma unroll
    for (int i = 0; i < 4; ++i)
#pragma unroll
        for (int j = 0; j < 8; ++j) acc[i][j] = 0.f;
    const float4* x4 = (const float4*)x;
    const float4* w14 = (const float4*)w1;
    for (int kc = 0; kc < 16; ++kc) {
#pragma unroll
        for (int j = 0; j < 2; ++j) {
            int idx = tx + 256 * j, r = idx >> 3, q = idx & 7;
            xs4[r * 9 + q] = x4[(row0 + r) * 128 + kc * 8 + q];
        }
#pragma unroll
        for (int j = 0; j < 4; ++j) {
            int idx = tx + 256 * j, k = idx >> 5, cq = idx & 31;
            w1s4[k * 33 + cq] = w14[(kc * 32 + k) * 32 + cq];
        }
        __syncthreads();
#pragma unroll 4
        for (int kk = 0; kk < 32; ++kk) {
            float4 b0 = w1s4[kk * 33 + ct * 2], b1q = w1s4[kk * 33 + ct * 2 + 1];
#pragma unroll
            for (int i = 0; i < 4; ++i) {
                float a = xsf[(r0 + i) * 36 + kk];
                acc[i][0] += a * b0.x; acc[i][1] += a * b0.y; acc[i][2] += a * b0.z; acc[i][3] += a * b0.w;
                acc[i][4] += a * b1q.x; acc[i][5] += a * b1q.y; acc[i][6] += a * b1q.z; acc[i][7] += a * b1q.w;
            }
        }
        __syncthreads();
    }
    float sc[8], sh[8], bb[8];
#pragma unroll
    for (int j = 0; j < 8; ++j) {
        int c = c0 + j;
        float s = gamma_[c] * rsqrtf(var_[c] + 1e-5f);
        sc[j] = s; sh[j] = beta_[c] - mean_[c] * s; bb[j] = b1[c];
    }
#pragma unroll
    for (int i = 0; i < 4; ++i) {
        float h[8];
#pragma unroll
        for (int j = 0; j < 8; ++j) { float v = fmaxf(acc[i][j] + bb[j], 0.f); h[j] = v * sc[j] + sh[j]; }
        hs4[(r0 + i) * 33 + ct * 2] = make_float4(h[0], h[1], h[2], h[3]);
        hs4[(r0 + i) * 33 + ct * 2 + 1] = make_float4(h[4], h[5], h[6], h[7]);
    }
    __syncthreads();
    const int tt = tx & 15, rt2 = tx >> 4, t0 = tt * 4, r0b = rt2 * 4;
    float a2[4][4];
#pragma unroll
    for (int i = 0; i < 4; ++i)
#pragma unroll
        for (int j = 0; j < 4; ++j) a2[i][j] = b2[t0 + j];
    const float4* w24 = (const float4*)w2;
#pragma unroll 4
    for (int c = 0; c < 128; ++c) {
        float4 wv = __ldg(&w24[c * 16 + tt]);
#pragma unroll
        for (int i = 0; i < 4; ++i) {
            float h = hsf[(r0b + i) * 132 + c];
            a2[i][0] += h * wv.x; a2[i][1] += h * wv.y; a2[i][2] += h * wv.z; a2[i][3] += h * wv.w;
        }
    }
    __syncthreads();
#pragma unroll
    for (int i = 0; i < 4; ++i)
        *(float4*)&ls[(r0b + i) * 68 + t0] = make_float4(a2[i][0], a2[i][1], a2[i][2], a2[i][3]);
    __syncthreads();
    if (tx < 64) {
        int row = row0 + tx;
        const float* lr = ls + tx * 68;
        float m = -1e30f, s = 0.f;
#pragma unroll 4
        for (int t = 0; t < 64; ++t) m = fmaxf(m, lr[t]);
#pragma unroll 4
        for (int t = 0; t < 64; ++t) s += expf(lr[t] - m);
        float inv = 1.f / s;
#pragma unroll 4
        for (int t = 0; t < 64; ++t) g_attn[t * B_TOTAL + row] = expf(lr[t] - m) * inv * (0.3f * resw[t]);
    }
}

// ---------- k_trees: 512 threads, single-pass bf16, 2 kc per stage ----------
__global__ __launch_bounds__(512, 1) void k_trees(
    const float* __restrict__ tree_b, const float* __restrict__ tree_temp,
    const float* __restrict__ leaf_values, float* __restrict__ out)
{
    extern __shared__ __align__(16) char smp[];
    const uint32_t sm = smem_u32(smp);
    const int tid = threadIdx.x, lane = tid & 31, wid = tid >> 5;
    const int wt = wid & 1;                 // tree within group
    const int wm = (wid >> 1) & 3;          // M tile (32 rows)
    const int wn = (wid >> 3) & 1;          // N half (4 ni each)
    const int row = tid & 127, part = tid >> 7;   // epilogue: 4 threads/row
    const int rowg = blockIdx.x * 128 + row;
    float* lg = (float*)(smp + OFF_LG);           // [128][72]
    const int miss = g_missing[rowg];

    float pred[NCLS];
#pragma unroll
    for (int c = 0; c < NCLS; ++c) pred[c] = 0.f;

    const unsigned char* xbase = g_xf + (size_t)blockIdx.x * 8 * 16384;

    // stage s (0..127): grp = s>>2, kc-pair = s&3 (covers kc 2*(s&3), 2*(s&3)+1)
    auto issue = [&](int s) {
        const int grp = s >> 2, kp = s & 3;
        const uint32_t buf = (uint32_t)(s & 1);
        const unsigned char* xsrc = xbase + (size_t)kp * 32768;
        const uint32_t xdst = sm + OFF_X + buf * 32768;
#pragma unroll
        for (int j = 0; j < 4; ++j) {
            int ch = tid + 512 * j;
            CP16(xdst + ch * 16, xsrc + ch * 16);
        }
        const unsigned char* wsrc0 = g_wf + ((size_t)(grp * 2) * 8 + kp * 2) * 8192;
        const uint32_t wdst = sm + OFF_W + buf * 32768;
#pragma unroll
        for (int j = 0; j < 2; ++j) {
            int ch = tid + 512 * j;
            CP16(wdst + ch * 16, wsrc0 + ch * 16);                    // tree0: 16KB (2 kc)
            CP16(wdst + 16384 + ch * 16, wsrc0 + 8 * 8192 + ch * 16); // tree1: 16KB
        }
        if (kp == 0) {
            const unsigned char* lsrc = (const unsigned char*)leaf_values + (size_t)grp * 5120;
            uint32_t ldst = sm + OFF_LEAF + (uint32_t)(grp & 1) * 5120;
            if (tid < 320) CP16(ldst + tid * 16, lsrc + tid * 16);
        }
    };

    float acc[2][4][4];
#pragma unroll
    for (int mi = 0; mi < 2; ++mi)
#pragma unroll
        for (int ni = 0; ni < 4; ++ni)
#pragma unroll
            for (int q = 0; q < 4; ++q) acc[mi][ni][q] = 0.f;

    issue(0);
    CPCOMMIT();

    for (int s = 0; s < 128; ++s) {
        if (s + 1 < 128) { issue(s + 1); CPCOMMIT(); CPWAIT1(); }
        else CPWAIT0();
        __syncthreads();
        const char* bx = smp + OFF_X + (s & 1) * 32768;
        const char* bw = smp + OFF_W + (s & 1) * 32768 + wt * 16384;
#pragma unroll
        for (int kh = 0; kh < 2; ++kh) {
#pragma unroll
            for (int ks = 0; ks < 4; ++ks) {
                uint4 ah[2];
#pragma unroll
                for (int mi = 0; mi < 2; ++mi)
                    ah[mi] = *(const uint4*)(bx + kh * 16384 +
                        (uint32_t)(((ks * 8 + wm * 2 + mi) * 32 + lane) * 16));
#pragma unroll
                for (int ni = 0; ni < 4; ++ni) {
                    uint2 b = *(const uint2*)(bw + kh * 8192 +
                        (uint32_t)(((ks * 8 + wn * 4 + ni) * 32 + lane) * 8));
#pragma unroll
                    for (int mi = 0; mi < 2; ++mi)
                        MMA2(acc[mi][ni], ah[mi], b.x, b.y);
                }
            }
        }
        __syncthreads();

        if ((s & 3) == 3) {
            const int grp = s >> 2;
            for (int tt = 0; tt < 2; ++tt) {
                const int t = grp * 2 + tt;
                if (wt == tt) {
#pragma unroll
                    for (int mi = 0; mi < 2; ++mi)
#pragma unroll
                        for (int ni = 0; ni < 4; ++ni) {
                            int r0 = wm * 32 + mi * 16 + (lane >> 2);
                            int c0 = wn * 32 + ni * 8 + (lane & 3) * 2;
                            *(float2*)&lg[r0 * 72 + c0] = make_float2(acc[mi][ni][0], acc[mi][ni][1]);
                            *(float2*)&lg[(r0 + 8) * 72 + c0] = make_float2(acc[mi][ni][2], acc[mi][ni][3]);
                        }
                }
                __syncthreads();
                {
                    float invt = 1.f / tree_temp[t];
#pragma unroll
                    for (int j = 0; j < 16; ++j) {
                        int n = part * 16 + j;
                        if (n < NNODES) {
                            float z = (lg[row * 72 + n] + tree_b[t * NNODES + n]) * invt;
                            z = fminf(fmaxf(z, -30.f), 30.f);
                            float d = __fdividef(1.f, 1.f + __expf(-z));
                            lg[row * 72 + n] = miss ? 0.5f : d;
                        }
                    }
                }
                __syncthreads();
                {
                    const float* dp = lg + row * 72;
                    const float* lf = (const float*)(smp + OFF_LEAF + (grp & 1) * 5120) + tt * 640;
                    float d0 = dp[0], d1 = dp[1], d2 = dp[2];
                    float r2[2], r4[4], r8[8];
                    r2[0] = d0; r2[1] = 1.f - d0;
                    r4[0] = r2[0] * d1; r4[2] = r2[0] - r4[0];
                    r4[1] = r2[1] * d2; r4[3] = r2[1] - r4[1];
#pragma unroll
                    for (int j = 0; j < 4; ++j) {
                        float d = dp[3 + j];
                        r8[j] = r4[j] * d; r8[j + 4] = r4[j] - r8[j];
                    }
                    float o[NCLS];
#pragma unroll
                    for (int c = 0; c < NCLS; ++c) o[c] = 0.f;
#pragma unroll
                    for (int j = 0; j < 8; ++j) {
                        int i = part * 8 + j;
                        float f3 = dp[7 + (i & 7)];   if ((i >> 3) & 1) f3 = 1.f - f3;
                        float f4 = dp[15 + (i & 15)]; if ((i >> 4) & 1) f4 = 1.f - f4;
                        float rr = r8[i & 7] * f3 * f4;
                        float d5 = dp[31 + i];
                        float pL = rr * d5, pR = rr - pL;
                        const float* lL = lf + i * 10;
                        const float* lR = lf + (i + 32) * 10;
#pragma unroll
                        for (int c = 0; c < NCLS; ++c) o[c] += pL * lL[c] + pR * lR[c];
                    }
                    float at = g_attn[t * B_TOTAL + rowg];
#pragma unroll
                    for (int c = 0; c < NCLS; ++c) pred[c] += at * o[c];
                }
                __syncthreads();
            }
#pragma unroll
            for (int mi = 0; mi < 2; ++mi)
#pragma unroll
                for (int ni = 0; ni < 4; ++ni)
#pragma unroll
                    for (int q = 0; q < 4; ++q) acc[mi][ni][q] = 0.f;
        }
    }

    // combine 4 parts + softmax
    float* pred_s = lg;   // 4 x 128 x 10 = 20K < 36K
#pragma unroll
    for (int c = 0; c < NCLS; ++c) pred_s[part * 1280 + row * 10 + c] = pred[c];
    __syncthreads();
    if (tid < 128) {
#pragma unroll
        for (int c = 0; c < NCLS; ++c)
            pred[c] = pred_s[row * 10 + c] + pred_s[1280 + row * 10 + c]
                    + pred_s[2560 + row * 10 + c] + pred_s[3840 + row * 10 + c];
        float m = pred[0];
#pragma unroll
        for (int c = 1; c < NCLS; ++c) m = fmaxf(m, pred[c]);
        float e[NCLS], s = 0.f;
#pragma unroll
        for (int c = 0; c < NCLS; ++c) { e[c] = expf(pred[c] - m); s += e[c]; }
        float inv = 1.f / s;
#pragma unroll
        for (int c = 0; c < NCLS; ++c) out[rowg * 10 + c] = e[c] * inv;
    }
}

// ---------- launcher ----------
extern "C" void kernel_launch(void* const* d_in, const int* in_sizes, int n_in,
                              void* d_out, int out_size) {
    const float* x = (const float*)d_in[0];
    const float* w1 = (const float*)d_in[1];
    const float* b1 = (const float*)d_in[2];
    const float* gm = (const float*)d_in[3];
    const float* bt = (const float*)d_in[4];
    const float* mn = (const float*)d_in[5];
    const float* vr = (const float*)d_in[6];
    const float* w2 = (const float*)d_in[7];
    const float* b2 = (const float*)d_in[8];
    const float* tw = (const float*)d_in[9];
    const float* tb = (const float*)d_in[10];
    const float* tt = (const float*)d_in[11];
    const float* lv = (const float*)d_in[12];
    const float* rw = (const float*)d_in[13];
    cudaFuncSetAttribute(k_trees, cudaFuncAttributeMaxDynamicSharedMemorySize, SMEM_SZ);
    k_prep_x<<<1024, 256>>>(x);
    k_prep_w<<<512, 256>>>(tw);
    k_attn<<<B_TOTAL / 64, 256>>>(x, w1, b1, gm, bt, mn, vr, w2, b2, rw);
    k_trees<<<128, 512, SMEM_SZ>>>(tb, tt, lv, (float*)d_out);
}